// round 2
// baseline (speedup 1.0000x reference)
#include <cuda_runtime.h>
#include <cstdint>

// ---------------------------------------------------------------------------
// PingHead on sm_103 (no 'a' features available -> legacy mma.sync tf32 path).
// out[m] = lin_b + sum_g lin_w[g] * (1-z)*n with gates from
// gi = x @ W_ih^T : M=65536, N=384 (3 gate blocks x 128), K=1024. h==0 so
// weight_hh is dead.
// CTA: 256 thr (8 warps, 2m x 4n), M_tile=128, all N=384 in register accum.
// 3-stage cp.async pipeline (K chunk = 32), ldmatrix + mma.m16n8k8.tf32,
// cvt.rna at consumption for unbiased tf32 rounding. Fused gate epilogue via
// smem gi buffer (reuses stage memory).
// ---------------------------------------------------------------------------

#define KCHUNKS 32
#define A_BYTES (128 * 128)                 // 128 rows x 32 f32
#define B_BYTES (384 * 128)                 // 384 rows x 32 f32
#define STAGE_BYTES (A_BYTES + B_BYTES)     // 64 KB
#define ROWP 385                            // gi row stride (floats), odd -> no conflicts
#define GI_BYTES (128 * ROWP * 4)           // 197120 > 3*STAGE_BYTES (196608)
#define SMEM_DYN (GI_BYTES + 1024)

__device__ __forceinline__ uint32_t smem_u32(const void* p) {
    uint32_t a;
    asm("{ .reg .u64 t; cvta.to.shared.u64 t, %1; cvt.u32.u64 %0, t; }" : "=r"(a) : "l"(p));
    return a;
}

__device__ __forceinline__ void cp_async16(uint32_t dst, const void* src) {
    asm volatile("cp.async.cg.shared.global [%0], [%1], 16;" :: "r"(dst), "l"(src) : "memory");
}
#define CP_COMMIT() asm volatile("cp.async.commit_group;" ::: "memory")
#define CP_WAIT1()  asm volatile("cp.async.wait_group 1;" ::: "memory")
#define CP_WAIT0()  asm volatile("cp.async.wait_group 0;" ::: "memory")

__device__ __forceinline__ void ldsm4(uint32_t* r, uint32_t addr) {
    asm volatile("ldmatrix.sync.aligned.m8n8.x4.shared.b16 {%0,%1,%2,%3}, [%4];"
                 : "=r"(r[0]), "=r"(r[1]), "=r"(r[2]), "=r"(r[3]) : "r"(addr));
}

__device__ __forceinline__ uint32_t cvt_tf32(uint32_t v) {
    uint32_t r;
    asm("cvt.rna.tf32.f32 %0, %1;" : "=r"(r) : "f"(__uint_as_float(v)));
    return r;
}

__device__ __forceinline__ void mma_tf32(float* d, const uint32_t* a, const uint32_t* b) {
    asm volatile("mma.sync.aligned.m16n8k8.row.col.f32.tf32.tf32.f32 "
                 "{%0,%1,%2,%3},{%4,%5,%6,%7},{%8,%9},{%0,%1,%2,%3};"
                 : "+f"(d[0]), "+f"(d[1]), "+f"(d[2]), "+f"(d[3])
                 : "r"(a[0]), "r"(a[1]), "r"(a[2]), "r"(a[3]), "r"(b[0]), "r"(b[1]));
}

__global__ void __launch_bounds__(256, 1)
ping_head_kernel(const float* __restrict__ x,
                 const float* __restrict__ w,
                 const float* __restrict__ b_ih,
                 const float* __restrict__ b_hh,
                 const float* __restrict__ lin_w,
                 const float* __restrict__ lin_b,
                 float* __restrict__ out) {
    extern __shared__ char dsm[];
    __shared__ float s_br[128], s_bz[128], s_bni[128], s_bnh[128], s_lw[128];

    const int tid = threadIdx.x;
    const int wid = tid >> 5;
    const int lane = tid & 31;
    const int m0 = blockIdx.x * 128;

    // 1024-align dynamic smem (swizzle pattern is relative to 1KB blocks)
    const uint32_t dsm_u = smem_u32(dsm);
    const uint32_t sb = (dsm_u + 1023u) & ~1023u;
    char* gi_base = dsm + (sb - dsm_u);

    if (tid < 128) {
        s_br[tid]  = b_ih[tid] + b_hh[tid];
        s_bz[tid]  = b_ih[128 + tid] + b_hh[128 + tid];
        s_bni[tid] = b_ih[256 + tid];
        s_bnh[tid] = b_hh[256 + tid];
        s_lw[tid]  = lin_w[tid];
    }

    // ---- stage copy: gmem fp32 -> smem (swizzled), 16 x 16B per thread ----
    auto copy_stage = [&](int kc) {
        const uint32_t sbase = sb + (uint32_t)(kc % 3) * STAGE_BYTES;
        const int koff = kc * 32;
#pragma unroll
        for (int ch = 0; ch < 16; ch++) {
            const int idx = tid + ch * 256;
            if (idx < 1024) {                      // A: 128 rows x 8 chunks
                const int row = idx >> 3, c = idx & 7;
                const float* src = x + (size_t)(m0 + row) * 1024 + koff + c * 4;
                const uint32_t doff = (uint32_t)(row * 128) + (((uint32_t)(c * 16)) ^ ((uint32_t)(row & 7) << 4));
                cp_async16(sbase + doff, src);
            } else {                               // B: 384 rows x 8 chunks
                const int bi = idx - 1024;
                const int row = bi >> 3, c = bi & 7;
                const float* src = w + (size_t)row * 1024 + koff + c * 4;
                const uint32_t doff = (uint32_t)A_BYTES + (uint32_t)(row * 128) +
                                      (((uint32_t)(c * 16)) ^ ((uint32_t)(row & 7) << 4));
                cp_async16(sbase + doff, src);
            }
        }
    };

    // ---- per-thread ldmatrix addressing ----
    const int warp_m = wid >> 2;          // 0..1 -> 64 rows each
    const int warp_n = wid & 3;           // 0..3 -> 96 cols each (12 n8 tiles)
    const int mb = warp_m * 64;
    const int nb = warp_n * 96;

    const int ri   = lane & 15;                         // A row within m16 tile
    const uint32_t sega = (uint32_t)((lane >> 4) << 4); // 0 / 16
    const uint32_t xpa  = (uint32_t)((ri & 7) << 4);
    const uint32_t a_root = (uint32_t)((mb + ri) * 128);

    const int rb   = (lane & 7) + (((lane >> 4) & 1) << 3);   // B row within tile-pair
    const uint32_t segb = (uint32_t)(((lane >> 3) & 1) << 4);
    const uint32_t xpb  = (uint32_t)((rb & 7) << 4);
    const uint32_t b_root = (uint32_t)A_BYTES + (uint32_t)((nb + rb) * 128);

    float acc[4][12][4];
#pragma unroll
    for (int t = 0; t < 4; t++)
#pragma unroll
        for (int j = 0; j < 12; j++)
#pragma unroll
            for (int q = 0; q < 4; q++) acc[t][j][q] = 0.0f;

    copy_stage(0); CP_COMMIT();
    copy_stage(1); CP_COMMIT();

    for (int kc = 0; kc < KCHUNKS; kc++) {
        CP_WAIT1();
        __syncthreads();
        if (kc + 2 < KCHUNKS) copy_stage(kc + 2);
        CP_COMMIT();

        const uint32_t stb = sb + (uint32_t)(kc % 3) * STAGE_BYTES;
#pragma unroll
        for (int s = 0; s < 4; s++) {
            const uint32_t sbytes = (uint32_t)(s * 32);
            uint32_t bf[6][4];
#pragma unroll
            for (int jp = 0; jp < 6; jp++) {
                const uint32_t addr = stb + b_root + (uint32_t)(jp * 2048) + ((sbytes + segb) ^ xpb);
                ldsm4(bf[jp], addr);
#pragma unroll
                for (int q = 0; q < 4; q++) bf[jp][q] = cvt_tf32(bf[jp][q]);
            }
#pragma unroll
            for (int t = 0; t < 4; t++) {
                uint32_t af[4];
                const uint32_t addr = stb + a_root + (uint32_t)(t * 2048) + ((sbytes + sega) ^ xpa);
                ldsm4(af, addr);
#pragma unroll
                for (int q = 0; q < 4; q++) af[q] = cvt_tf32(af[q]);
#pragma unroll
                for (int j = 0; j < 12; j++) {
                    mma_tf32(acc[t][j], af, &bf[j >> 1][(j & 1) * 2]);
                }
            }
        }
    }

    CP_WAIT0();
    __syncthreads();   // all warps done reading stage smem before gi overwrite

    // ---- spill C fragments to smem gi[128][ROWP] ----
    float* gi = reinterpret_cast<float*>(gi_base);
    {
        const int r0 = mb + (lane >> 2);
        const int c0 = nb + 2 * (lane & 3);
#pragma unroll
        for (int t = 0; t < 4; t++) {
            const int row = r0 + t * 16;
#pragma unroll
            for (int j = 0; j < 12; j++) {
                const int col = c0 + j * 8;
                gi[row * ROWP + col]           = acc[t][j][0];
                gi[row * ROWP + col + 1]       = acc[t][j][1];
                gi[(row + 8) * ROWP + col]     = acc[t][j][2];
                gi[(row + 8) * ROWP + col + 1] = acc[t][j][3];
            }
        }
    }
    __syncthreads();

    // ---- fused gate epilogue: 2 threads per row (even/odd g interleave) ----
    {
        const int row = tid >> 1;
        const int half = tid & 1;
        const float* gr = gi + row * ROWP;
        float a = 0.0f;
#pragma unroll 4
        for (int k = 0; k < 64; k++) {
            const int g = 2 * k + half;
            const float xr = gr[g] + s_br[g];
            const float xz = gr[128 + g] + s_bz[g];
            const float r  = 1.0f / (1.0f + __expf(-xr));
            const float zc = 1.0f / (1.0f + __expf(xz));          // 1 - z
            const float xn = gr[256 + g] + s_bni[g] + r * s_bnh[g];
            const float e  = __expf(-2.0f * fabsf(xn));
            float th = __fdividef(1.0f - e, 1.0f + e);
            th = copysignf(th, xn);
            a += s_lw[g] * zc * th;
        }
        a += __shfl_xor_sync(0xffffffffu, a, 1);
        if (half == 0) out[m0 + row] = a + lin_b[0];
    }
}

extern "C" void kernel_launch(void* const* d_in, const int* in_sizes, int n_in,
                              void* d_out, int out_size) {
    const float* x     = (const float*)d_in[0];
    const float* w_ih  = (const float*)d_in[1];
    // d_in[2] = weight_hh: mathematically dead (hidden state is always zero)
    const float* b_ih  = (const float*)d_in[3];
    const float* b_hh  = (const float*)d_in[4];
    const float* lin_w = (const float*)d_in[5];
    const float* lin_b = (const float*)d_in[6];
    float* out = (float*)d_out;

    cudaFuncSetAttribute(ping_head_kernel,
                         cudaFuncAttributeMaxDynamicSharedMemorySize, SMEM_DYN);
    ping_head_kernel<<<512, 256, SMEM_DYN>>>(x, w_ih, b_ih, b_hh, lin_w, lin_b, out);
}